// round 7
// baseline (speedup 1.0000x reference)
#include <cuda_runtime.h>
#include <cuda_fp16.h>
#include <cstdint>
#include <cstddef>

typedef unsigned long long u64;
typedef unsigned int u32;

#define B_TOT 2048
#define N_TOK 49
#define CDIM  256
#define NHEAD 8
#define HDIM  32
#define M_ROWS (B_TOT * N_TOK)      // 100352
#define NN 2401                      // 49*49
#define NNP 2432                     // padded row (16B-aligned rows)

// -------- scratch (device globals: no allocation allowed) --------
__device__ __align__(16) float g_q[(size_t)B_TOT * NHEAD * N_TOK * HDIM];
__device__ __align__(16) float g_k[(size_t)B_TOT * NHEAD * N_TOK * HDIM];
__device__ __align__(16) float g_v[(size_t)B_TOT * NHEAD * N_TOK * HDIM];
__device__ __align__(16) __half g_xh[(size_t)M_ROWS * 512];    // x hi|lo fp16
__device__ __align__(16) __half g_ah[(size_t)M_ROWS * 512];    // attn-out hi|lo
__device__ __align__(16) __half g_wqkv[768 * 256];             // plain fp16
__device__ __align__(16) __half g_wproj[256 * 256];            // plain fp16
__device__ float g_emb[64 * NHEAD * NN];                       // exp(mask+bias)
__device__ __align__(16) float g_efg[(size_t)B_TOT * NNP];     // exp(fg), padded
__device__ __align__(16) float g_ebg[(size_t)B_TOT * NNP];     // exp(bg), padded

// -------- packed-fp32 helpers (fma.rn.f32x2) --------
__device__ __forceinline__ u64 pack2(float x, float y) {
    u64 r; asm("mov.b64 %0,{%1,%2};" : "=l"(r) : "f"(x), "f"(y)); return r;
}
__device__ __forceinline__ u64 pack2b(float x) {
    u64 r; asm("mov.b64 %0,{%1,%1};" : "=l"(r) : "f"(x)); return r;
}
__device__ __forceinline__ u64 ffma2(u64 a, u64 b, u64 c) {
    u64 d; asm("fma.rn.f32x2 %0,%1,%2,%3;" : "=l"(d) : "l"(a), "l"(b), "l"(c)); return d;
}
__device__ __forceinline__ float2 unpack2(u64 v) {
    float lo, hi; asm("mov.b64 {%0,%1},%2;" : "=f"(lo), "=f"(hi) : "l"(v));
    return make_float2(lo, hi);
}

// -------- smem / async-copy / mma helpers (standard PTX, sm_80-safe) --------
__device__ __forceinline__ u32 smem_u32(const void* p) {
    u32 a; asm("{ .reg .u64 t; cvta.to.shared.u64 t,%1; cvt.u32.u64 %0,t; }" : "=r"(a) : "l"(p));
    return a;
}
__device__ __forceinline__ void cp16(u32 dst, const void* src) {
    asm volatile("cp.async.cg.shared.global [%0], [%1], 16;" :: "r"(dst), "l"(src));
}
__device__ __forceinline__ u32 lds32(u32 addr) {
    u32 v; asm volatile("ld.shared.b32 %0,[%1];" : "=r"(v) : "r"(addr)); return v;
}
__device__ __forceinline__ void hmma16816(float* c, const u32* a, const u32* b) {
    asm volatile(
        "mma.sync.aligned.m16n8k16.row.col.f32.f16.f16.f32 "
        "{%0,%1,%2,%3},{%4,%5,%6,%7},{%8,%9},{%0,%1,%2,%3};"
        : "+f"(c[0]), "+f"(c[1]), "+f"(c[2]), "+f"(c[3])
        : "r"(a[0]), "r"(a[1]), "r"(a[2]), "r"(a[3]), "r"(b[0]), "r"(b[1]));
}

// -------- fp32 -> (hi|lo) fp16: [R,256] f32 -> [R,512] half --------
__global__ void conv_h(const float* __restrict__ src, __half* __restrict__ dst, int rows) {
    int t = blockIdx.x * blockDim.x + threadIdx.x;
    if (t >= rows * 64) return;
    int m = t >> 6, k4 = (t & 63) << 2;
    float4 v = *(const float4*)(src + (size_t)m * 256 + k4);
    __half h0 = __float2half_rn(v.x), h1 = __float2half_rn(v.y);
    __half h2 = __float2half_rn(v.z), h3 = __float2half_rn(v.w);
    __half2 hh, ll;
    __half* dh = dst + (size_t)m * 512 + k4;
    hh.x = h0; hh.y = h1; *(__half2*)(dh) = hh;
    hh.x = h2; hh.y = h3; *(__half2*)(dh + 2) = hh;
    ll.x = __float2half_rn(v.x - __half2float(h0));
    ll.y = __float2half_rn(v.y - __half2float(h1));
    *(__half2*)(dh + 256) = ll;
    ll.x = __float2half_rn(v.z - __half2float(h2));
    ll.y = __float2half_rn(v.w - __half2float(h3));
    *(__half2*)(dh + 258) = ll;
}

// -------- fp32 -> plain fp16 --------
__global__ void conv_h1(const float* __restrict__ src, __half* __restrict__ dst, int rows) {
    int t = blockIdx.x * blockDim.x + threadIdx.x;
    if (t >= rows * 64) return;
    int m = t >> 6, k4 = (t & 63) << 2;
    float4 v = *(const float4*)(src + (size_t)m * 256 + k4);
    __half2 a;
    __half* dh = dst + (size_t)m * 256 + k4;
    a.x = __float2half_rn(v.x); a.y = __float2half_rn(v.y); *(__half2*)(dh) = a;
    a.x = __float2half_rn(v.z); a.y = __float2half_rn(v.w); *(__half2*)(dh + 2) = a;
}

// -------- precompute exp(mask[w][i][j] + bias[h][i][j]) --------
__global__ void emb_kernel(const float* __restrict__ table,
                           const float* __restrict__ mask) {
    int t = blockIdx.x * blockDim.x + threadIdx.x;
    if (t >= 64 * NHEAD * NN) return;
    int w   = t / (NHEAD * NN);
    int rem = t - w * (NHEAD * NN);
    int h   = rem / NN;
    int ij  = rem - h * NN;
    int i = ij / 49, j = ij - i * 49;
    int ri = i / 7, ci = i - ri * 7;
    int rj = j / 7, cj = j - rj * 7;
    int idx = (ri - rj + 6) * 13 + (ci - cj + 6);
    g_emb[t] = __expf(mask[w * NN + ij] + table[idx * NHEAD + h]);
}

// -------- precompute exp(fg), exp(bg) into 16B-aligned padded rows --------
__global__ void exp_fb(const float* __restrict__ fg, const float* __restrict__ bg) {
    int t = blockIdx.x * blockDim.x + threadIdx.x;
    if (t >= B_TOT * NN) return;
    int b = t / NN, ij = t - b * NN;
    size_t d = (size_t)b * NNP + ij;
    g_efg[d] = __expf(fg[t]);
    g_ebg[d] = __expf(bg[t]);
}

// -------- HMMA GEMM: C[M,Ncols] = A[M,256] @ W[Ncols,256]^T + bias --------
// A as [rows,512] fp16 (hi|lo); W plain fp16 [rows,256].
// 2-term split: D += Ah*Bh + Al*Bh. CTA 128x128, 4 warps, warp tile 64x64.
#define TSTRIDE 112                 // bytes per smem row (56 halfs)
#define TILE_B  (128 * TSTRIDE)     // 14336
#define STAGE_B (3 * TILE_B)        // 43008 (Ah, Al, Bh)
#define GEMM_SMEM (2 * STAGE_B)     // 86016

template<int MODE>
__global__ void __launch_bounds__(128) hgemm(const __half* __restrict__ Ah_,
                                             const __half* __restrict__ Wh_,
                                             const float* __restrict__ bias,
                                             float* __restrict__ out) {
    extern __shared__ char smem[];
    const u32 sb = smem_u32(smem);
    const int tid = threadIdx.x;
    const int wid = tid >> 5, lane = tid & 31;
    const int g = lane >> 2, t = lane & 3;
    const int wm = wid >> 1, wn = wid & 1;          // warp grid 2m x 2n
    const int bn = blockIdx.x, bm = blockIdx.y;

    const char* Asrc = (const char*)(Ah_ + (size_t)(bm * 128) * 512);
    const char* Wsrc = (const char*)(Wh_ + (size_t)(bn * 128) * 256);

    float acc[4][8][4];
#pragma unroll
    for (int i = 0; i < 4; i++)
#pragma unroll
        for (int j = 0; j < 8; j++)
#pragma unroll
            for (int q = 0; q < 4; q++) acc[i][j][q] = 0.f;

    auto issue = [&](int s) {
        const u32 drow = sb + (s & 1) * STAGE_B + tid * TSTRIDE;
        const size_t goA = (size_t)tid * 1024 + (size_t)s * 64;
        const size_t goW = (size_t)tid * 512  + (size_t)s * 64;
#pragma unroll
        for (int c = 0; c < 4; c++) {
            cp16(drow + 0 * TILE_B + c * 16, Asrc + goA + c * 16);
            cp16(drow + 1 * TILE_B + c * 16, Asrc + goA + 512 + c * 16);
            cp16(drow + 2 * TILE_B + c * 16, Wsrc + goW + c * 16);
        }
        asm volatile("cp.async.commit_group;" ::: "memory");
    };

    issue(0);
    for (int s = 0; s < 8; s++) {
        if (s < 7) {
            issue(s + 1);
            asm volatile("cp.async.wait_group 1;" ::: "memory");
        } else {
            asm volatile("cp.async.wait_group 0;" ::: "memory");
        }
        __syncthreads();

        const u32 stb = sb + (s & 1) * STAGE_B;
        const u32 A0 = stb, A1 = stb + TILE_B, B0 = stb + 2 * TILE_B;
#pragma unroll
        for (int s2 = 0; s2 < 2; s2++) {
            const u32 w0 = (s2 * 8 + t) * 4;
            u32 ah[4][4], al[4][4], bh[8][2];
#pragma unroll
            for (int mt = 0; mt < 4; mt++) {
                const u32 r0 = (wm * 64 + mt * 16 + g) * TSTRIDE + w0;
                const u32 r1 = r0 + 8 * TSTRIDE;
                ah[mt][0] = lds32(A0 + r0);      ah[mt][1] = lds32(A0 + r1);
                ah[mt][2] = lds32(A0 + r0 + 16); ah[mt][3] = lds32(A0 + r1 + 16);
                al[mt][0] = lds32(A1 + r0);      al[mt][1] = lds32(A1 + r1);
                al[mt][2] = lds32(A1 + r0 + 16); al[mt][3] = lds32(A1 + r1 + 16);
            }
#pragma unroll
            for (int nt = 0; nt < 8; nt++) {
                const u32 rb = (wn * 64 + nt * 8 + g) * TSTRIDE + w0;
                bh[nt][0] = lds32(B0 + rb); bh[nt][1] = lds32(B0 + rb + 16);
            }
#pragma unroll
            for (int mt = 0; mt < 4; mt++)
#pragma unroll
                for (int nt = 0; nt < 8; nt++) {
                    hmma16816(acc[mt][nt], ah[mt], bh[nt]);
                    hmma16816(acc[mt][nt], al[mt], bh[nt]);
                }
        }
        __syncthreads();
    }

    // ---- epilogue ----
#pragma unroll
    for (int nt = 0; nt < 8; nt++) {
        const int col0 = bn * 128 + wn * 64 + nt * 8 + t * 2;
        const float b0 = bias[col0], b1 = bias[col0 + 1];
        if (MODE == 0) {
            const int part = col0 >> 8;
            const int h = (col0 >> 5) & 7;
            const int d0 = col0 & 31;
            const float scale = (part == 0) ? 0.17677669529663687f : 1.0f;
            float* dstb = (part == 0) ? g_q : ((part == 1) ? g_k : g_v);
#pragma unroll
            for (int mt = 0; mt < 4; mt++) {
                const float* c = acc[mt][nt];
#pragma unroll
                for (int rr = 0; rr < 2; rr++) {
                    const int m = bm * 128 + wm * 64 + mt * 16 + g + rr * 8;
                    const int bidx = m / 49, tok = m - bidx * 49;
                    float* dst = dstb + ((size_t)(bidx * 8 + h) * 49 + tok) * 32 + d0;
                    float2 v;
                    v.x = (c[rr * 2 + 0] + b0) * scale;
                    v.y = (c[rr * 2 + 1] + b1) * scale;
                    *(float2*)dst = v;
                }
            }
        } else {
#pragma unroll
            for (int mt = 0; mt < 4; mt++) {
                const float* c = acc[mt][nt];
#pragma unroll
                for (int rr = 0; rr < 2; rr++) {
                    const int m = bm * 128 + wm * 64 + mt * 16 + g + rr * 8;
                    float2 v;
                    v.x = c[rr * 2 + 0] + b0;
                    v.y = c[rr * 2 + 1] + b1;
                    *(float2*)(out + (size_t)m * 256 + col0) = v;
                }
            }
        }
    }
}

// -------- fused window attention: one block per (batch, head) --------
// exp(fg)/exp(bg) prefetched via cp.async, overlapped with QK compute.
#define QS 33    // sQ row stride
#define ES 53    // sE row stride

__global__ void __launch_bounds__(128) attn_kernel() {
    __shared__ float sQ[52 * QS];
    __shared__ __align__(16) float sKt[32 * 52];
    __shared__ __align__(16) float sV[49 * 32];
    __shared__ float sE[52 * ES];
    __shared__ __align__(16) float sFG[2404];
    __shared__ __align__(16) float sBG[2404];

    const int bh = blockIdx.x;
    const int b = bh >> 3, h = bh & 7;
    const int tid = threadIdx.x;
    const int warp = tid >> 5, lane = tid & 31;

    // prefetch exp(fg)/exp(bg) rows (601 x 16B each), overlapped with QK
    {
        const u32 sfg = smem_u32(sFG), sbg = smem_u32(sBG);
        const char* efg = (const char*)(g_efg + (size_t)b * NNP);
        const char* ebg = (const char*)(g_ebg + (size_t)b * NNP);
        for (int i = tid; i < 601; i += 128) {
            cp16(sfg + i * 16, efg + i * 16);
            cp16(sbg + i * 16, ebg + i * 16);
        }
        asm volatile("cp.async.commit_group;" ::: "memory");
    }

    // zero pads: sQ rows 49..51, sKt cols 49..51
    if (tid < 96) {
        int r = 49 + tid / 32, k = tid % 32;
        sQ[r * QS + k] = 0.f;
        int kk = tid / 3, j = 49 + tid % 3;
        sKt[kk * 52 + j] = 0.f;
    }

    const size_t base = (size_t)bh * (N_TOK * HDIM);
    for (int f = tid; f < 392; f += 128) {
        int j = f >> 3, k4 = (f & 7) << 2;
        float4 qv = ((const float4*)(g_q + base))[f];
        sQ[j * QS + k4 + 0] = qv.x; sQ[j * QS + k4 + 1] = qv.y;
        sQ[j * QS + k4 + 2] = qv.z; sQ[j * QS + k4 + 3] = qv.w;
        ((float4*)sV)[f] = ((const float4*)(g_v + base))[f];
        float4 kv = ((const float4*)(g_k + base))[f];
        sKt[(k4 + 0) * 52 + j] = kv.x; sKt[(k4 + 1) * 52 + j] = kv.y;
        sKt[(k4 + 2) * 52 + j] = kv.z; sKt[(k4 + 3) * 52 + j] = kv.w;
    }
    __syncthreads();

    // ---- S = Q K^T, E0 = exp(S)*emb; 4x4 register tiles ----
    const float* embh = g_emb + (size_t)((b & 63) * NHEAD + h) * NN;
    for (int job = tid; job < 169; job += 128) {
        int iP = job / 13, jq = job - iP * 13;
        int i0 = iP * 4, j0 = jq * 4;
        u64 acc[4][2];
#pragma unroll
        for (int r = 0; r < 4; r++) { acc[r][0] = 0; acc[r][1] = 0; }
        const float* kt = sKt + j0;
        const float* q0 = sQ + i0 * QS;
#pragma unroll 8
        for (int k = 0; k < 32; k++) {
            float4 kv = *(const float4*)(kt + k * 52);
            u64 k0p = pack2(kv.x, kv.y), k1p = pack2(kv.z, kv.w);
#pragma unroll
            for (int r = 0; r < 4; r++) {
                u64 qp = pack2b(q0[r * QS + k]);
                acc[r][0] = ffma2(qp, k0p, acc[r][0]);
                acc[r][1] = ffma2(qp, k1p, acc[r][1]);
            }
        }
#pragma unroll
        for (int r = 0; r < 4; r++) {
            int row = i0 + r;
            if (row < 49) {
                float* er = sE + row * ES;
                const float* m0 = embh + row * 49;
                float2 v0 = unpack2(acc[r][0]), v1 = unpack2(acc[r][1]);
                er[j0] = __expf(v0.x) * m0[j0];
                if (j0 + 1 < 49) er[j0 + 1] = __expf(v0.y) * m0[j0 + 1];
                if (j0 + 2 < 49) er[j0 + 2] = __expf(v1.x) * m0[j0 + 2];
                if (j0 + 3 < 49) er[j0 + 3] = __expf(v1.y) * m0[j0 + 3];
            }
        }
    }
    asm volatile("cp.async.wait_group 0;" ::: "memory");
    __syncthreads();

    // ---- one-pass triple softmax (warp per row), efg/ebg from smem ----
    for (int row = warp; row < 49; row += 4) {
        float* er = sE + row * ES;
        const float* fgr = sFG + row * 49;
        const float* bgr = sBG + row * 49;
        bool ok = lane < 17;
        float e0  = er[lane];
        float fga = fgr[lane], bga = bgr[lane];
        float e0b = 0.f, fgb = 0.f, bgb = 0.f;
        if (ok) {
            e0b = er[lane + 32];
            fgb = fgr[lane + 32];
            bgb = bgr[lane + 32];
        }
        float s0 = e0 + e0b;
        float sf = e0 * fga + e0b * fgb;
        float sb2 = e0 * bga + e0b * bgb;
#pragma unroll
        for (int o = 16; o; o >>= 1) {
            s0  += __shfl_xor_sync(0xffffffffu, s0, o);
            sf  += __shfl_xor_sync(0xffffffffu, sf, o);
            sb2 += __shfl_xor_sync(0xffffffffu, sb2, o);
        }
        float r0 = 1.f / s0, rf = 1.f / sf, rb = 1.f / sb2;
        er[lane] = e0 * (r0 + rf * fga - rb * bga);
        if (ok) er[lane + 32] = e0b * (r0 + rf * fgb - rb * bgb);
    }
    __syncthreads();

    // ---- O = P @ V; write fp16 hi|lo ----
    if (tid < 104) {
        int iP = tid >> 3, dq = tid & 7;
        int i0 = iP * 4, d0 = dq * 4;
        u64 acc[4][2];
#pragma unroll
        for (int r = 0; r < 4; r++) { acc[r][0] = 0; acc[r][1] = 0; }
        const float* vp = sV + d0;
        const float* p0 = sE + i0 * ES;
#pragma unroll 7
        for (int j = 0; j < 49; j++) {
            float4 vv = *(const float4*)(vp + j * 32);
            u64 v0 = pack2(vv.x, vv.y), v1 = pack2(vv.z, vv.w);
#pragma unroll
            for (int r = 0; r < 4; r++) {
                u64 pp = pack2b(p0[r * ES + j]);
                acc[r][0] = ffma2(pp, v0, acc[r][0]);
                acc[r][1] = ffma2(pp, v1, acc[r][1]);
            }
        }
#pragma unroll
        for (int r = 0; r < 4; r++) {
            int row = i0 + r;
            if (row < 49) {
                __half* o0 = g_ah + ((size_t)(b * 49 + row)) * 512 + h * 32 + d0;
                float2 x0 = unpack2(acc[r][0]), x1 = unpack2(acc[r][1]);
                __half h0 = __float2half_rn(x0.x), h1 = __float2half_rn(x0.y);
                __half h2 = __float2half_rn(x1.x), h3 = __float2half_rn(x1.y);
                __half2 hh, ll;
                hh.x = h0; hh.y = h1; *(__half2*)(o0) = hh;
                hh.x = h2; hh.y = h3; *(__half2*)(o0 + 2) = hh;
                ll.x = __float2half_rn(x0.x - __half2float(h0));
                ll.y = __float2half_rn(x0.y - __half2float(h1));
                *(__half2*)(o0 + 256) = ll;
                ll.x = __float2half_rn(x1.x - __half2float(h2));
                ll.y = __float2half_rn(x1.y - __half2float(h3));
                *(__half2*)(o0 + 258) = ll;
            }
        }
    }
}

extern "C" void kernel_launch(void* const* d_in, const int* in_sizes, int n_in,
                              void* d_out, int out_size) {
    const float* x      = (const float*)d_in[0];
    const float* mask   = (const float*)d_in[1];
    const float* fg     = (const float*)d_in[2];
    const float* bg     = (const float*)d_in[3];
    const float* qkv_w  = (const float*)d_in[4];
    const float* qkv_b  = (const float*)d_in[5];
    const float* proj_w = (const float*)d_in[6];
    const float* proj_b = (const float*)d_in[7];
    const float* table  = (const float*)d_in[8];
    float* out = (float*)d_out;

    cudaFuncSetAttribute(hgemm<0>, cudaFuncAttributeMaxDynamicSharedMemorySize, GEMM_SMEM);
    cudaFuncSetAttribute(hgemm<1>, cudaFuncAttributeMaxDynamicSharedMemorySize, GEMM_SMEM);

    __half* xh;    cudaGetSymbolAddress((void**)&xh,    g_xh);
    __half* wqkv;  cudaGetSymbolAddress((void**)&wqkv,  g_wqkv);
    __half* wproj; cudaGetSymbolAddress((void**)&wproj, g_wproj);
    __half* ah;    cudaGetSymbolAddress((void**)&ah,    g_ah);

    conv_h<<<(M_ROWS * 64 + 255) / 256, 256>>>(x, xh, M_ROWS);
    conv_h1<<<(768 * 64 + 255) / 256, 256>>>(qkv_w, wqkv, 768);
    conv_h1<<<(256 * 64 + 255) / 256, 256>>>(proj_w, wproj, 256);
    emb_kernel<<<(64 * NHEAD * NN + 255) / 256, 256>>>(table, mask);
    exp_fb<<<(B_TOT * NN + 255) / 256, 256>>>(fg, bg);

    hgemm<0><<<dim3(6, 784), 128, GEMM_SMEM>>>(xh, wqkv, qkv_b, nullptr);
    attn_kernel<<<B_TOT * NHEAD, 128>>>();
    hgemm<1><<<dim3(2, 784), 128, GEMM_SMEM>>>(ah, wproj, proj_b, out);
}

// round 8
// speedup vs baseline: 1.2282x; 1.2282x over previous
#include <cuda_runtime.h>
#include <cuda_fp16.h>
#include <cstdint>
#include <cstddef>

typedef unsigned long long u64;
typedef unsigned int u32;

#define B_TOT 2048
#define N_TOK 49
#define CDIM  256
#define NHEAD 8
#define HDIM  32
#define M_ROWS (B_TOT * N_TOK)      // 100352
#define NN 2401                      // 49*49

// -------- scratch (device globals: no allocation allowed) --------
__device__ __align__(16) float g_q[(size_t)B_TOT * NHEAD * N_TOK * HDIM];
__device__ __align__(16) float g_k[(size_t)B_TOT * NHEAD * N_TOK * HDIM];
__device__ __align__(16) float g_v[(size_t)B_TOT * NHEAD * N_TOK * HDIM];
__device__ __align__(16) __half g_xh[(size_t)M_ROWS * 512];    // x hi|lo fp16
__device__ __align__(16) __half g_ah[(size_t)M_ROWS * 512];    // attn-out hi|lo
__device__ __align__(16) __half g_wqkv[768 * 256];             // plain fp16
__device__ __align__(16) __half g_wproj[256 * 256];            // plain fp16
__device__ float g_emb[64 * NHEAD * NN];   // exp(mask[w] + rel_pos_bias[h])

// -------- packed-fp32 helpers (fma.rn.f32x2) --------
__device__ __forceinline__ u64 pack2(float x, float y) {
    u64 r; asm("mov.b64 %0,{%1,%2};" : "=l"(r) : "f"(x), "f"(y)); return r;
}
__device__ __forceinline__ u64 pack2b(float x) {
    u64 r; asm("mov.b64 %0,{%1,%1};" : "=l"(r) : "f"(x)); return r;
}
__device__ __forceinline__ u64 ffma2(u64 a, u64 b, u64 c) {
    u64 d; asm("fma.rn.f32x2 %0,%1,%2,%3;" : "=l"(d) : "l"(a), "l"(b), "l"(c)); return d;
}
__device__ __forceinline__ float2 unpack2(u64 v) {
    float lo, hi; asm("mov.b64 {%0,%1},%2;" : "=f"(lo), "=f"(hi) : "l"(v));
    return make_float2(lo, hi);
}

// -------- smem / async-copy / mma helpers (standard PTX, sm_80-safe) --------
__device__ __forceinline__ u32 smem_u32(const void* p) {
    u32 a; asm("{ .reg .u64 t; cvta.to.shared.u64 t,%1; cvt.u32.u64 %0,t; }" : "=r"(a) : "l"(p));
    return a;
}
__device__ __forceinline__ void cp16(u32 dst, const void* src) {
    asm volatile("cp.async.cg.shared.global [%0], [%1], 16;" :: "r"(dst), "l"(src));
}
__device__ __forceinline__ void ldm4(u32* r, u32 addr) {
    asm volatile("ldmatrix.sync.aligned.m8n8.x4.shared.b16 {%0,%1,%2,%3},[%4];"
                 : "=r"(r[0]), "=r"(r[1]), "=r"(r[2]), "=r"(r[3]) : "r"(addr));
}
__device__ __forceinline__ void hmma16816(float* c, const u32* a, const u32* b) {
    asm volatile(
        "mma.sync.aligned.m16n8k16.row.col.f32.f16.f16.f32 "
        "{%0,%1,%2,%3},{%4,%5,%6,%7},{%8,%9},{%0,%1,%2,%3};"
        : "+f"(c[0]), "+f"(c[1]), "+f"(c[2]), "+f"(c[3])
        : "r"(a[0]), "r"(a[1]), "r"(a[2]), "r"(a[3]), "r"(b[0]), "r"(b[1]));
}

// -------- fp32 -> (hi|lo) fp16: [R,256] f32 -> [R,512] half --------
__global__ void conv_h(const float* __restrict__ src, __half* __restrict__ dst, int rows) {
    int t = blockIdx.x * blockDim.x + threadIdx.x;
    if (t >= rows * 64) return;
    int m = t >> 6, k4 = (t & 63) << 2;
    float4 v = *(const float4*)(src + (size_t)m * 256 + k4);
    __half h0 = __float2half_rn(v.x), h1 = __float2half_rn(v.y);
    __half h2 = __float2half_rn(v.z), h3 = __float2half_rn(v.w);
    __half2 hh, ll;
    __half* dh = dst + (size_t)m * 512 + k4;
    hh.x = h0; hh.y = h1; *(__half2*)(dh) = hh;
    hh.x = h2; hh.y = h3; *(__half2*)(dh + 2) = hh;
    ll.x = __float2half_rn(v.x - __half2float(h0));
    ll.y = __float2half_rn(v.y - __half2float(h1));
    *(__half2*)(dh + 256) = ll;
    ll.x = __float2half_rn(v.z - __half2float(h2));
    ll.y = __float2half_rn(v.w - __half2float(h3));
    *(__half2*)(dh + 258) = ll;
}

// -------- fp32 -> plain fp16 --------
__global__ void conv_h1(const float* __restrict__ src, __half* __restrict__ dst, int rows) {
    int t = blockIdx.x * blockDim.x + threadIdx.x;
    if (t >= rows * 64) return;
    int m = t >> 6, k4 = (t & 63) << 2;
    float4 v = *(const float4*)(src + (size_t)m * 256 + k4);
    __half2 a;
    __half* dh = dst + (size_t)m * 256 + k4;
    a.x = __float2half_rn(v.x); a.y = __float2half_rn(v.y); *(__half2*)(dh) = a;
    a.x = __float2half_rn(v.z); a.y = __float2half_rn(v.w); *(__half2*)(dh + 2) = a;
}

// -------- precompute exp(mask[w][i][j] + bias[h][i][j]) --------
__global__ void emb_kernel(const float* __restrict__ table,
                           const float* __restrict__ mask) {
    int t = blockIdx.x * blockDim.x + threadIdx.x;
    if (t >= 64 * NHEAD * NN) return;
    int w   = t / (NHEAD * NN);
    int rem = t - w * (NHEAD * NN);
    int h   = rem / NN;
    int ij  = rem - h * NN;
    int i = ij / 49, j = ij - i * 49;
    int ri = i / 7, ci = i - ri * 7;
    int rj = j / 7, cj = j - rj * 7;
    int idx = (ri - rj + 6) * 13 + (ci - cj + 6);
    g_emb[t] = __expf(mask[w * NN + ij] + table[idx * NHEAD + h]);
}

// -------- HMMA GEMM: C[M,Ncols] = A[M,256] @ W[Ncols,256]^T + bias --------
// A as [rows,512] fp16 (hi|lo); W plain fp16 [rows,256].
// 2-term split: D += Ah*Bh + Al*Bh. CTA 128x128, 8 warps (2m x 4n), warp 64x32.
// Fragments via ldmatrix.x4 (rows at stride 112B -> conflict-free).
#define TSTRIDE 112                 // bytes per smem row (56 halfs)
#define TILE_B  (128 * TSTRIDE)     // 14336
#define STAGE_B (3 * TILE_B)        // 43008 (Ah, Al, Bh)
#define GEMM_SMEM (2 * STAGE_B)     // 86016

template<int MODE>
__global__ void __launch_bounds__(256) hgemm(const __half* __restrict__ Ah_,
                                             const __half* __restrict__ Wh_,
                                             const float* __restrict__ bias,
                                             float* __restrict__ out) {
    extern __shared__ char smem[];
    const u32 sb = smem_u32(smem);
    const int tid = threadIdx.x;
    const int wid = tid >> 5, lane = tid & 31;
    const int g = lane >> 2, t = lane & 3;
    const int wm = wid >> 2, wn = wid & 3;          // warp grid 2m x 4n
    const int bn = blockIdx.x, bm = blockIdx.y;

    const char* Asrc = (const char*)(Ah_ + (size_t)(bm * 128) * 512);
    const char* Wsrc = (const char*)(Wh_ + (size_t)(bn * 128) * 256);

    float acc[4][4][4];
#pragma unroll
    for (int i = 0; i < 4; i++)
#pragma unroll
        for (int j = 0; j < 4; j++)
#pragma unroll
            for (int q = 0; q < 4; q++) acc[i][j][q] = 0.f;

    const int r_ld = tid >> 2, c4 = tid & 3;        // 64 rows per 256-thread pass

    auto issue = [&](int s) {
        const u32 dbase = sb + (s & 1) * STAGE_B;
#pragma unroll
        for (int i = 0; i < 2; i++) {
            const int r = r_ld + i * 64;
            const u32 d = dbase + r * TSTRIDE + c4 * 16;
            const size_t goA = (size_t)r * 1024 + (size_t)s * 64 + c4 * 16;
            const size_t goW = (size_t)r * 512  + (size_t)s * 64 + c4 * 16;
            cp16(d + 0 * TILE_B, Asrc + goA);          // Ah
            cp16(d + 1 * TILE_B, Asrc + goA + 512);    // Al
            cp16(d + 2 * TILE_B, Wsrc + goW);          // Bh
        }
        asm volatile("cp.async.commit_group;" ::: "memory");
    };

    // ldmatrix per-lane address offsets (within a tile region)
    // A (m16k16): lanes 0-15 -> rows 0..15 kb+0; lanes 16-31 -> rows 0..15 kb+16
    const u32 a_lrow = (lane & 15);
    const u32 a_lcol = (lane >> 4) << 4;
    // B (n16k16, two n8k16 frags): q = lane>>3
    // q0: n=l&7,kb0 ; q1: n=l&7,kb16 ; q2: n=8+(l&7),kb0 ; q3: n=8+(l&7),kb16
    const u32 b_lrow = ((lane >> 4) << 3) + (lane & 7);
    const u32 b_lcol = ((lane >> 3) & 1) << 4;

    issue(0);
    for (int s = 0; s < 8; s++) {
        if (s < 7) {
            issue(s + 1);
            asm volatile("cp.async.wait_group 1;" ::: "memory");
        } else {
            asm volatile("cp.async.wait_group 0;" ::: "memory");
        }
        __syncthreads();

        const u32 stb = sb + (s & 1) * STAGE_B;
        const u32 A0 = stb, A1 = stb + TILE_B, B0 = stb + 2 * TILE_B;
#pragma unroll
        for (int s2 = 0; s2 < 2; s2++) {
            const u32 kbase = s2 * 32;
            u32 ah[4][4], al[4][4], bh[4][2];
#pragma unroll
            for (int mt = 0; mt < 4; mt++) {
                const u32 ra = (wm * 64 + mt * 16 + a_lrow) * TSTRIDE + kbase + a_lcol;
                ldm4(ah[mt], A0 + ra);
                ldm4(al[mt], A1 + ra);
            }
#pragma unroll
            for (int nt2 = 0; nt2 < 2; nt2++) {
                u32 btmp[4];
                const u32 rb = (wn * 32 + nt2 * 16 + b_lrow) * TSTRIDE + kbase + b_lcol;
                ldm4(btmp, B0 + rb);
                bh[nt2 * 2 + 0][0] = btmp[0]; bh[nt2 * 2 + 0][1] = btmp[1];
                bh[nt2 * 2 + 1][0] = btmp[2]; bh[nt2 * 2 + 1][1] = btmp[3];
            }
#pragma unroll
            for (int mt = 0; mt < 4; mt++)
#pragma unroll
                for (int nt = 0; nt < 4; nt++) {
                    hmma16816(acc[mt][nt], ah[mt], bh[nt]);
                    hmma16816(acc[mt][nt], al[mt], bh[nt]);
                }
        }
        __syncthreads();
    }

    // ---- epilogue ----
#pragma unroll
    for (int nt = 0; nt < 4; nt++) {
        const int col0 = bn * 128 + wn * 32 + nt * 8 + t * 2;
        const float b0 = bias[col0], b1 = bias[col0 + 1];
        if (MODE == 0) {
            const int part = col0 >> 8;
            const int h = (col0 >> 5) & 7;
            const int d0 = col0 & 31;
            const float scale = (part == 0) ? 0.17677669529663687f : 1.0f;
            float* dstb = (part == 0) ? g_q : ((part == 1) ? g_k : g_v);
#pragma unroll
            for (int mt = 0; mt < 4; mt++) {
                const float* c = acc[mt][nt];
#pragma unroll
                for (int rr = 0; rr < 2; rr++) {
                    const int m = bm * 128 + wm * 64 + mt * 16 + g + rr * 8;
                    const int bidx = m / 49, tok = m - bidx * 49;
                    float* dst = dstb + ((size_t)(bidx * 8 + h) * 49 + tok) * 32 + d0;
                    float2 v;
                    v.x = (c[rr * 2 + 0] + b0) * scale;
                    v.y = (c[rr * 2 + 1] + b1) * scale;
                    *(float2*)dst = v;
                }
            }
        } else {
#pragma unroll
            for (int mt = 0; mt < 4; mt++) {
                const float* c = acc[mt][nt];
#pragma unroll
                for (int rr = 0; rr < 2; rr++) {
                    const int m = bm * 128 + wm * 64 + mt * 16 + g + rr * 8;
                    float2 v;
                    v.x = c[rr * 2 + 0] + b0;
                    v.y = c[rr * 2 + 1] + b1;
                    *(float2*)(out + (size_t)m * 256 + col0) = v;
                }
            }
        }
    }
}

// -------- fused window attention: one block per (batch, head) --------
// (round-6 proven version: fg/bg from gmem in one-pass softmax)
#define QS 33    // sQ row stride (conflict fix)
#define ES 53    // sE row stride (conflict fix)

__global__ void __launch_bounds__(128) attn_kernel(const float* __restrict__ fg,
                                                   const float* __restrict__ bg) {
    __shared__ float sQ[52 * QS];
    __shared__ __align__(16) float sKt[32 * 52];
    __shared__ __align__(16) float sV[49 * 32];
    __shared__ float sE[52 * ES];

    const int bh = blockIdx.x;
    const int b = bh >> 3, h = bh & 7;
    const int tid = threadIdx.x;
    const int warp = tid >> 5, lane = tid & 31;

    // zero pads: sQ rows 49..51, sKt cols 49..51
    if (tid < 96) {
        int r = 49 + tid / 32, k = tid % 32;
        sQ[r * QS + k] = 0.f;
        int kk = tid / 3, j = 49 + tid % 3;
        sKt[kk * 52 + j] = 0.f;
    }

    const size_t base = (size_t)bh * (N_TOK * HDIM);
    for (int f = tid; f < 392; f += 128) {
        int j = f >> 3, k4 = (f & 7) << 2;
        float4 qv = ((const float4*)(g_q + base))[f];
        sQ[j * QS + k4 + 0] = qv.x; sQ[j * QS + k4 + 1] = qv.y;
        sQ[j * QS + k4 + 2] = qv.z; sQ[j * QS + k4 + 3] = qv.w;
        ((float4*)sV)[f] = ((const float4*)(g_v + base))[f];
        float4 kv = ((const float4*)(g_k + base))[f];
        sKt[(k4 + 0) * 52 + j] = kv.x; sKt[(k4 + 1) * 52 + j] = kv.y;
        sKt[(k4 + 2) * 52 + j] = kv.z; sKt[(k4 + 3) * 52 + j] = kv.w;
    }
    __syncthreads();

    // ---- S = Q K^T, E0 = exp(S)*emb; 4x4 register tiles ----
    const float* embh = g_emb + (size_t)((b & 63) * NHEAD + h) * NN;
    for (int job = tid; job < 169; job += 128) {
        int iP = job / 13, jq = job - iP * 13;
        int i0 = iP * 4, j0 = jq * 4;
        u64 acc[4][2];
#pragma unroll
        for (int r = 0; r < 4; r++) { acc[r][0] = 0; acc[r][1] = 0; }
        const float* kt = sKt + j0;
        const float* q0 = sQ + i0 * QS;
#pragma unroll 8
        for (int k = 0; k < 32; k++) {
            float4 kv = *(const float4*)(kt + k * 52);
            u64 k0p = pack2(kv.x, kv.y), k1p = pack2(kv.z, kv.w);
#pragma unroll
            for (int r = 0; r < 4; r++) {
                u64 qp = pack2b(q0[r * QS + k]);
                acc[r][0] = ffma2(qp, k0p, acc[r][0]);
                acc[r][1] = ffma2(qp, k1p, acc[r][1]);
            }
        }
#pragma unroll
        for (int r = 0; r < 4; r++) {
            int row = i0 + r;
            if (row < 49) {
                float* er = sE + row * ES;
                const float* m0 = embh + row * 49;
                float2 v0 = unpack2(acc[r][0]), v1 = unpack2(acc[r][1]);
                er[j0] = __expf(v0.x) * m0[j0];
                if (j0 + 1 < 49) er[j0 + 1] = __expf(v0.y) * m0[j0 + 1];
                if (j0 + 2 < 49) er[j0 + 2] = __expf(v1.x) * m0[j0 + 2];
                if (j0 + 3 < 49) er[j0 + 3] = __expf(v1.y) * m0[j0 + 3];
            }
        }
    }
    __syncthreads();

    // ---- one-pass triple softmax (warp per row), fg/bg from gmem ----
    for (int row = warp; row < 49; row += 4) {
        float* er = sE + row * ES;
        const float* fgr = fg + (size_t)b * NN + row * 49;
        const float* bgr = bg + (size_t)b * NN + row * 49;
        bool ok = lane < 17;
        float e0  = er[lane];
        float fga = __expf(fgr[lane]), bga = __expf(bgr[lane]);
        float e0b = 0.f, fgb = 0.f, bgb = 0.f;
        if (ok) {
            e0b = er[lane + 32];
            fgb = __expf(fgr[lane + 32]);
            bgb = __expf(bgr[lane + 32]);
        }
        float s0 = e0 + e0b;
        float sf = e0 * fga + e0b * fgb;
        float sb2 = e0 * bga + e0b * bgb;
#pragma unroll
        for (int o = 16; o; o >>= 1) {
            s0  += __shfl_xor_sync(0xffffffffu, s0, o);
            sf  += __shfl_xor_sync(0xffffffffu, sf, o);
            sb2 += __shfl_xor_sync(0xffffffffu, sb2, o);
        }
        float r0 = 1.f / s0, rf = 1.f / sf, rb = 1.f / sb2;
        er[lane] = e0 * (r0 + rf * fga - rb * bga);
        if (ok) er[lane + 32] = e0b * (r0 + rf * fgb - rb * bgb);
    }
    __syncthreads();

    // ---- O = P @ V; 4x4 tiles; write fp16 hi|lo ----
    if (tid < 104) {
        int iP = tid >> 3, dq = tid & 7;
        int i0 = iP * 4, d0 = dq * 4;
        u64 acc[4][2];
#pragma unroll
        for (int r = 0; r < 4; r++) { acc[r][0] = 0; acc[r][1] = 0; }
        const float* vp = sV + d0;
        const float* p0 = sE + i0 * ES;
#pragma unroll 7
        for (int j = 0; j < 49; j++) {
            float4 vv = *(const float4*)(vp + j * 32);
            u64 v0 = pack2(vv.x, vv.y), v1 = pack2(vv.z, vv.w);
#pragma unroll
            for (int r = 0; r < 4; r++) {
                u64 pp = pack2b(p0[r * ES + j]);
                acc[r][0] = ffma2(pp, v0, acc[r][0]);
                acc[r][1] = ffma2(pp, v1, acc[r][1]);
            }
        }
#pragma unroll
        for (int r = 0; r < 4; r++) {
            int row = i0 + r;
            if (row < 49) {
                __half* o0 = g_ah + ((size_t)(b * 49 + row)) * 512 + h * 32 + d0;
                float2 x0 = unpack2(acc[r][0]), x1 = unpack2(acc[r][1]);
                __half h0 = __float2half_rn(x0.x), h1 = __float2half_rn(x0.y);
                __half h2 = __float2half_rn(x1.x), h3 = __float2half_rn(x1.y);
                __half2 hh, ll;
                hh.x = h0; hh.y = h1; *(__half2*)(o0) = hh;
                hh.x = h2; hh.y = h3; *(__half2*)(o0 + 2) = hh;
                ll.x = __float2half_rn(x0.x - __half2float(h0));
                ll.y = __float2half_rn(x0.y - __half2float(h1));
                *(__half2*)(o0 + 256) = ll;
                ll.x = __float2half_rn(x1.x - __half2float(h2));
                ll.y = __float2half_rn(x1.y - __half2float(h3));
                *(__half2*)(o0 + 258) = ll;
            }
        }
    }
}

extern "C" void kernel_launch(void* const* d_in, const int* in_sizes, int n_in,
                              void* d_out, int out_size) {
    const float* x      = (const float*)d_in[0];
    const float* mask   = (const float*)d_in[1];
    const float* fg     = (const float*)d_in[2];
    const float* bg     = (const float*)d_in[3];
    const float* qkv_w  = (const float*)d_in[4];
    const float* qkv_b  = (const float*)d_in[5];
    const float* proj_w = (const float*)d_in[6];
    const float* proj_b = (const float*)d_in[7];
    const float* table  = (const float*)d_in[8];
    float* out = (float*)d_out;

    cudaFuncSetAttribute(hgemm<0>, cudaFuncAttributeMaxDynamicSharedMemorySize, GEMM_SMEM);
    cudaFuncSetAttribute(hgemm<1>, cudaFuncAttributeMaxDynamicSharedMemorySize, GEMM_SMEM);

    __half* xh;    cudaGetSymbolAddress((void**)&xh,    g_xh);
    __half* wqkv;  cudaGetSymbolAddress((void**)&wqkv,  g_wqkv);
    __half* wproj; cudaGetSymbolAddress((void**)&wproj, g_wproj);
    __half* ah;    cudaGetSymbolAddress((void**)&ah,    g_ah);

    conv_h<<<(M_ROWS * 64 + 255) / 256, 256>>>(x, xh, M_ROWS);
    conv_h1<<<(768 * 64 + 255) / 256, 256>>>(qkv_w, wqkv, 768);
    conv_h1<<<(256 * 64 + 255) / 256, 256>>>(proj_w, wproj, 256);
    emb_kernel<<<(64 * NHEAD * NN + 255) / 256, 256>>>(table, mask);

    hgemm<0><<<dim3(6, 784), 256, GEMM_SMEM>>>(xh, wqkv, qkv_b, nullptr);
    attn_kernel<<<B_TOT * NHEAD, 128>>>(fg, bg);
    hgemm<1><<<dim3(2, 784), 256, GEMM_SMEM>>>(ah, wproj, proj_b, out);
}

// round 9
// speedup vs baseline: 1.5338x; 1.2489x over previous
#include <cuda_runtime.h>
#include <cuda_fp16.h>
#include <cstdint>
#include <cstddef>

typedef unsigned long long u64;
typedef unsigned int u32;

#define B_TOT 2048
#define N_TOK 49
#define CDIM  256
#define NHEAD 8
#define HDIM  32
#define M_ROWS (B_TOT * N_TOK)      // 100352
#define NN 2401                      // 49*49

// -------- scratch (device globals: no allocation allowed) --------
__device__ __align__(16) float g_q[(size_t)B_TOT * NHEAD * N_TOK * HDIM];
__device__ __align__(16) float g_k[(size_t)B_TOT * NHEAD * N_TOK * HDIM];
__device__ __align__(16) float g_v[(size_t)B_TOT * NHEAD * N_TOK * HDIM];
__device__ __align__(16) __half g_xh[(size_t)M_ROWS * 256];    // x fp16
__device__ __align__(16) __half g_ah[(size_t)M_ROWS * 256];    // attn-out fp16
__device__ __align__(16) __half g_wqkv[768 * 256];             // fp16
__device__ __align__(16) __half g_wproj[256 * 256];            // fp16
__device__ float g_emb[64 * NHEAD * NN];   // exp(mask[w] + rel_pos_bias[h])

// -------- packed-fp32 helpers (fma.rn.f32x2) --------
__device__ __forceinline__ u64 pack2(float x, float y) {
    u64 r; asm("mov.b64 %0,{%1,%2};" : "=l"(r) : "f"(x), "f"(y)); return r;
}
__device__ __forceinline__ u64 pack2b(float x) {
    u64 r; asm("mov.b64 %0,{%1,%1};" : "=l"(r) : "f"(x)); return r;
}
__device__ __forceinline__ u64 ffma2(u64 a, u64 b, u64 c) {
    u64 d; asm("fma.rn.f32x2 %0,%1,%2,%3;" : "=l"(d) : "l"(a), "l"(b), "l"(c)); return d;
}
__device__ __forceinline__ float2 unpack2(u64 v) {
    float lo, hi; asm("mov.b64 {%0,%1},%2;" : "=f"(lo), "=f"(hi) : "l"(v));
    return make_float2(lo, hi);
}

// -------- smem / async-copy / mma helpers (standard PTX, sm_80-safe) --------
__device__ __forceinline__ u32 smem_u32(const void* p) {
    u32 a; asm("{ .reg .u64 t; cvta.to.shared.u64 t,%1; cvt.u32.u64 %0,t; }" : "=r"(a) : "l"(p));
    return a;
}
__device__ __forceinline__ void cp16(u32 dst, const void* src) {
    asm volatile("cp.async.cg.shared.global [%0], [%1], 16;" :: "r"(dst), "l"(src));
}
__device__ __forceinline__ void ldm4(u32* r, u32 addr) {
    asm volatile("ldmatrix.sync.aligned.m8n8.x4.shared.b16 {%0,%1,%2,%3},[%4];"
                 : "=r"(r[0]), "=r"(r[1]), "=r"(r[2]), "=r"(r[3]) : "r"(addr));
}
__device__ __forceinline__ void hmma16816(float* c, const u32* a, const u32* b) {
    asm volatile(
        "mma.sync.aligned.m16n8k16.row.col.f32.f16.f16.f32 "
        "{%0,%1,%2,%3},{%4,%5,%6,%7},{%8,%9},{%0,%1,%2,%3};"
        : "+f"(c[0]), "+f"(c[1]), "+f"(c[2]), "+f"(c[3])
        : "r"(a[0]), "r"(a[1]), "r"(a[2]), "r"(a[3]), "r"(b[0]), "r"(b[1]));
}

// -------- fp32 -> fp16: [R,256] f32 -> [R,256] half --------
__global__ void conv_h1(const float* __restrict__ src, __half* __restrict__ dst, int rows) {
    int t = blockIdx.x * blockDim.x + threadIdx.x;
    if (t >= rows * 64) return;
    int m = t >> 6, k4 = (t & 63) << 2;
    float4 v = *(const float4*)(src + (size_t)m * 256 + k4);
    __half2 a;
    __half* dh = dst + (size_t)m * 256 + k4;
    a.x = __float2half_rn(v.x); a.y = __float2half_rn(v.y); *(__half2*)(dh) = a;
    a.x = __float2half_rn(v.z); a.y = __float2half_rn(v.w); *(__half2*)(dh + 2) = a;
}

// -------- precompute exp(mask[w][i][j] + bias[h][i][j]) --------
__global__ void emb_kernel(const float* __restrict__ table,
                           const float* __restrict__ mask) {
    int t = blockIdx.x * blockDim.x + threadIdx.x;
    if (t >= 64 * NHEAD * NN) return;
    int w   = t / (NHEAD * NN);
    int rem = t - w * (NHEAD * NN);
    int h   = rem / NN;
    int ij  = rem - h * NN;
    int i = ij / 49, j = ij - i * 49;
    int ri = i / 7, ci = i - ri * 7;
    int rj = j / 7, cj = j - rj * 7;
    int idx = (ri - rj + 6) * 13 + (ci - cj + 6);
    g_emb[t] = __expf(mask[w * NN + ij] + table[idx * NHEAD + h]);
}

// -------- HMMA GEMM (1-term fp16): C = A[M,256] @ W[N,256]^T + bias --------
// CTA 128x128, 8 warps (2m x 4n), warp 64x32, BK=32 sliced x8, double-buffered.
// Fragments via ldmatrix.x4 (rows at stride 112B -> conflict-free).
#define TSTRIDE 112                 // bytes per smem row
#define TILE_B  (128 * TSTRIDE)     // 14336
#define STAGE_B (2 * TILE_B)        // 28672 (A, B)
#define GEMM_SMEM (2 * STAGE_B)     // 57344

template<int MODE>
__global__ void __launch_bounds__(256) hgemm(const __half* __restrict__ Ah_,
                                             const __half* __restrict__ Wh_,
                                             const float* __restrict__ bias,
                                             float* __restrict__ out) {
    extern __shared__ char smem[];
    const u32 sb = smem_u32(smem);
    const int tid = threadIdx.x;
    const int wid = tid >> 5, lane = tid & 31;
    const int g = lane >> 2, t = lane & 3;
    const int wm = wid >> 2, wn = wid & 3;          // warp grid 2m x 4n
    const int bn = blockIdx.x, bm = blockIdx.y;

    const char* Asrc = (const char*)(Ah_ + (size_t)(bm * 128) * 256);
    const char* Wsrc = (const char*)(Wh_ + (size_t)(bn * 128) * 256);

    float acc[4][4][4];
#pragma unroll
    for (int i = 0; i < 4; i++)
#pragma unroll
        for (int j = 0; j < 4; j++)
#pragma unroll
            for (int q = 0; q < 4; q++) acc[i][j][q] = 0.f;

    const int r_ld = tid >> 2, c4 = tid & 3;        // 64 rows per 256-thread pass

    auto issue = [&](int s) {
        const u32 dbase = sb + (s & 1) * STAGE_B;
#pragma unroll
        for (int i = 0; i < 2; i++) {
            const int r = r_ld + i * 64;
            const u32 d = dbase + r * TSTRIDE + c4 * 16;
            const size_t go = (size_t)r * 512 + (size_t)s * 64 + c4 * 16;
            cp16(d + 0 * TILE_B, Asrc + go);
            cp16(d + 1 * TILE_B, Wsrc + go);
        }
        asm volatile("cp.async.commit_group;" ::: "memory");
    };

    // ldmatrix per-lane offsets
    const u32 a_lrow = (lane & 15);
    const u32 a_lcol = (lane >> 4) << 4;
    const u32 b_lrow = ((lane >> 4) << 3) + (lane & 7);
    const u32 b_lcol = ((lane >> 3) & 1) << 4;

    issue(0);
    for (int s = 0; s < 8; s++) {
        if (s < 7) {
            issue(s + 1);
            asm volatile("cp.async.wait_group 1;" ::: "memory");
        } else {
            asm volatile("cp.async.wait_group 0;" ::: "memory");
        }
        __syncthreads();

        const u32 stb = sb + (s & 1) * STAGE_B;
        const u32 A0 = stb, B0 = stb + TILE_B;
#pragma unroll
        for (int s2 = 0; s2 < 2; s2++) {
            const u32 kbase = s2 * 32;
            u32 ah[4][4], bh[4][2];
#pragma unroll
            for (int mt = 0; mt < 4; mt++) {
                const u32 ra = (wm * 64 + mt * 16 + a_lrow) * TSTRIDE + kbase + a_lcol;
                ldm4(ah[mt], A0 + ra);
            }
#pragma unroll
            for (int nt2 = 0; nt2 < 2; nt2++) {
                u32 btmp[4];
                const u32 rb = (wn * 32 + nt2 * 16 + b_lrow) * TSTRIDE + kbase + b_lcol;
                ldm4(btmp, B0 + rb);
                bh[nt2 * 2 + 0][0] = btmp[0]; bh[nt2 * 2 + 0][1] = btmp[1];
                bh[nt2 * 2 + 1][0] = btmp[2]; bh[nt2 * 2 + 1][1] = btmp[3];
            }
#pragma unroll
            for (int mt = 0; mt < 4; mt++)
#pragma unroll
                for (int nt = 0; nt < 4; nt++)
                    hmma16816(acc[mt][nt], ah[mt], bh[nt]);
        }
        __syncthreads();
    }

    // ---- epilogue ----
#pragma unroll
    for (int nt = 0; nt < 4; nt++) {
        const int col0 = bn * 128 + wn * 32 + nt * 8 + t * 2;
        const float b0 = bias[col0], b1 = bias[col0 + 1];
        if (MODE == 0) {
            const int part = col0 >> 8;
            const int h = (col0 >> 5) & 7;
            const int d0 = col0 & 31;
            const float scale = (part == 0) ? 0.17677669529663687f : 1.0f;
            float* dstb = (part == 0) ? g_q : ((part == 1) ? g_k : g_v);
#pragma unroll
            for (int mt = 0; mt < 4; mt++) {
                const float* c = acc[mt][nt];
#pragma unroll
                for (int rr = 0; rr < 2; rr++) {
                    const int m = bm * 128 + wm * 64 + mt * 16 + g + rr * 8;
                    const int bidx = m / 49, tok = m - bidx * 49;
                    float* dst = dstb + ((size_t)(bidx * 8 + h) * 49 + tok) * 32 + d0;
                    float2 v;
                    v.x = (c[rr * 2 + 0] + b0) * scale;
                    v.y = (c[rr * 2 + 1] + b1) * scale;
                    *(float2*)dst = v;
                }
            }
        } else {
#pragma unroll
            for (int mt = 0; mt < 4; mt++) {
                const float* c = acc[mt][nt];
#pragma unroll
                for (int rr = 0; rr < 2; rr++) {
                    const int m = bm * 128 + wm * 64 + mt * 16 + g + rr * 8;
                    float2 v;
                    v.x = c[rr * 2 + 0] + b0;
                    v.y = c[rr * 2 + 1] + b1;
                    *(float2*)(out + (size_t)m * 256 + col0) = v;
                }
            }
        }
    }
}

// -------- fused window attention: one block per (batch, head) --------
// (round-8 proven version; epilogue now writes plain fp16)
#define QS 33    // sQ row stride (conflict fix)
#define ES 53    // sE row stride (conflict fix)

__global__ void __launch_bounds__(128) attn_kernel(const float* __restrict__ fg,
                                                   const float* __restrict__ bg) {
    __shared__ float sQ[52 * QS];
    __shared__ __align__(16) float sKt[32 * 52];
    __shared__ __align__(16) float sV[49 * 32];
    __shared__ float sE[52 * ES];

    const int bh = blockIdx.x;
    const int b = bh >> 3, h = bh & 7;
    const int tid = threadIdx.x;
    const int warp = tid >> 5, lane = tid & 31;

    // zero pads: sQ rows 49..51, sKt cols 49..51
    if (tid < 96) {
        int r = 49 + tid / 32, k = tid % 32;
        sQ[r * QS + k] = 0.f;
        int kk = tid / 3, j = 49 + tid % 3;
        sKt[kk * 52 + j] = 0.f;
    }

    const size_t base = (size_t)bh * (N_TOK * HDIM);
    for (int f = tid; f < 392; f += 128) {
        int j = f >> 3, k4 = (f & 7) << 2;
        float4 qv = ((const float4*)(g_q + base))[f];
        sQ[j * QS + k4 + 0] = qv.x; sQ[j * QS + k4 + 1] = qv.y;
        sQ[j * QS + k4 + 2] = qv.z; sQ[j * QS + k4 + 3] = qv.w;
        ((float4*)sV)[f] = ((const float4*)(g_v + base))[f];
        float4 kv = ((const float4*)(g_k + base))[f];
        sKt[(k4 + 0) * 52 + j] = kv.x; sKt[(k4 + 1) * 52 + j] = kv.y;
        sKt[(k4 + 2) * 52 + j] = kv.z; sKt[(k4 + 3) * 52 + j] = kv.w;
    }
    __syncthreads();

    // ---- S = Q K^T, E0 = exp(S)*emb; 4x4 register tiles ----
    const float* embh = g_emb + (size_t)((b & 63) * NHEAD + h) * NN;
    for (int job = tid; job < 169; job += 128) {
        int iP = job / 13, jq = job - iP * 13;
        int i0 = iP * 4, j0 = jq * 4;
        u64 acc[4][2];
#pragma unroll
        for (int r = 0; r < 4; r++) { acc[r][0] = 0; acc[r][1] = 0; }
        const float* kt = sKt + j0;
        const float* q0 = sQ + i0 * QS;
#pragma unroll 8
        for (int k = 0; k < 32; k++) {
            float4 kv = *(const float4*)(kt + k * 52);
            u64 k0p = pack2(kv.x, kv.y), k1p = pack2(kv.z, kv.w);
#pragma unroll
            for (int r = 0; r < 4; r++) {
                u64 qp = pack2b(q0[r * QS + k]);
                acc[r][0] = ffma2(qp, k0p, acc[r][0]);
                acc[r][1] = ffma2(qp, k1p, acc[r][1]);
            }
        }
#pragma unroll
        for (int r = 0; r < 4; r++) {
            int row = i0 + r;
            if (row < 49) {
                float* er = sE + row * ES;
                const float* m0 = embh + row * 49;
                float2 v0 = unpack2(acc[r][0]), v1 = unpack2(acc[r][1]);
                er[j0] = __expf(v0.x) * m0[j0];
                if (j0 + 1 < 49) er[j0 + 1] = __expf(v0.y) * m0[j0 + 1];
                if (j0 + 2 < 49) er[j0 + 2] = __expf(v1.x) * m0[j0 + 2];
                if (j0 + 3 < 49) er[j0 + 3] = __expf(v1.y) * m0[j0 + 3];
            }
        }
    }
    __syncthreads();

    // ---- one-pass triple softmax (warp per row), fg/bg from gmem ----
    for (int row = warp; row < 49; row += 4) {
        float* er = sE + row * ES;
        const float* fgr = fg + (size_t)b * NN + row * 49;
        const float* bgr = bg + (size_t)b * NN + row * 49;
        bool ok = lane < 17;
        float e0  = er[lane];
        float fga = __expf(fgr[lane]), bga = __expf(bgr[lane]);
        float e0b = 0.f, fgb = 0.f, bgb = 0.f;
        if (ok) {
            e0b = er[lane + 32];
            fgb = __expf(fgr[lane + 32]);
            bgb = __expf(bgr[lane + 32]);
        }
        float s0 = e0 + e0b;
        float sf = e0 * fga + e0b * fgb;
        float sb2 = e0 * bga + e0b * bgb;
#pragma unroll
        for (int o = 16; o; o >>= 1) {
            s0  += __shfl_xor_sync(0xffffffffu, s0, o);
            sf  += __shfl_xor_sync(0xffffffffu, sf, o);
            sb2 += __shfl_xor_sync(0xffffffffu, sb2, o);
        }
        float r0 = 1.f / s0, rf = 1.f / sf, rb = 1.f / sb2;
        er[lane] = e0 * (r0 + rf * fga - rb * bga);
        if (ok) er[lane + 32] = e0b * (r0 + rf * fgb - rb * bgb);
    }
    __syncthreads();

    // ---- O = P @ V; 4x4 tiles; write plain fp16 ----
    if (tid < 104) {
        int iP = tid >> 3, dq = tid & 7;
        int i0 = iP * 4, d0 = dq * 4;
        u64 acc[4][2];
#pragma unroll
        for (int r = 0; r < 4; r++) { acc[r][0] = 0; acc[r][1] = 0; }
        const float* vp = sV + d0;
        const float* p0 = sE + i0 * ES;
#pragma unroll 7
        for (int j = 0; j < 49; j++) {
            float4 vv = *(const float4*)(vp + j * 32);
            u64 v0 = pack2(vv.x, vv.y), v1 = pack2(vv.z, vv.w);
#pragma unroll
            for (int r = 0; r < 4; r++) {
                u64 pp = pack2b(p0[r * ES + j]);
                acc[r][0] = ffma2(pp, v0, acc[r][0]);
                acc[r][1] = ffma2(pp, v1, acc[r][1]);
            }
        }
#pragma unroll
        for (int r = 0; r < 4; r++) {
            int row = i0 + r;
            if (row < 49) {
                __half* o0 = g_ah + ((size_t)(b * 49 + row)) * 256 + h * 32 + d0;
                float2 x0 = unpack2(acc[r][0]), x1 = unpack2(acc[r][1]);
                __half2 hh;
                hh.x = __float2half_rn(x0.x); hh.y = __float2half_rn(x0.y);
                *(__half2*)(o0) = hh;
                hh.x = __float2half_rn(x1.x); hh.y = __float2half_rn(x1.y);
                *(__half2*)(o0 + 2) = hh;
            }
        }
    }
}

extern "C" void kernel_launch(void* const* d_in, const int* in_sizes, int n_in,
                              void* d_out, int out_size) {
    const float* x      = (const float*)d_in[0];
    const float* mask   = (const float*)d_in[1];
    const float* fg     = (const float*)d_in[2];
    const float* bg     = (const float*)d_in[3];
    const float* qkv_w  = (const float*)d_in[4];
    const float* qkv_b  = (const float*)d_in[5];
    const float* proj_w = (const float*)d_in[6];
    const float* proj_b = (const float*)d_in[7];
    const float* table  = (const float*)d_in[8];
    float* out = (float*)d_out;

    cudaFuncSetAttribute(hgemm<0>, cudaFuncAttributeMaxDynamicSharedMemorySize, GEMM_SMEM);
    cudaFuncSetAttribute(hgemm<1>, cudaFuncAttributeMaxDynamicSharedMemorySize, GEMM_SMEM);

    __half* xh;    cudaGetSymbolAddress((void**)&xh,    g_xh);
    __half* wqkv;  cudaGetSymbolAddress((void**)&wqkv,  g_wqkv);
    __half* wproj; cudaGetSymbolAddress((void**)&wproj, g_wproj);
    __half* ah;    cudaGetSymbolAddress((void**)&ah,    g_ah);

    conv_h1<<<(M_ROWS * 64 + 255) / 256, 256>>>(x, xh, M_ROWS);
    conv_h1<<<(768 * 64 + 255) / 256, 256>>>(qkv_w, wqkv, 768);
    conv_h1<<<(256 * 64 + 255) / 256, 256>>>(proj_w, wproj, 256);
    emb_kernel<<<(64 * NHEAD * NN + 255) / 256, 256>>>(table, mask);

    hgemm<0><<<dim3(6, 784), 256, GEMM_SMEM>>>(xh, wqkv, qkv_b, nullptr);
    attn_kernel<<<B_TOT * NHEAD, 128>>>(fg, bg);
    hgemm<1><<<dim3(2, 784), 256, GEMM_SMEM>>>(ah, wproj, proj_b, out);
}